// round 14
// baseline (speedup 1.0000x reference)
#include <cuda_runtime.h>

typedef unsigned long long u64;
static const unsigned FULL = 0xFFFFFFFFu;

// ---- packed f32x2 helpers ----
__device__ __forceinline__ u64 pk2(float lo, float hi) {
    u64 r;
    asm("mov.b64 %0, {%1, %2};" : "=l"(r) : "f"(lo), "f"(hi));
    return r;
}
__device__ __forceinline__ void upk2(u64 a, float& lo, float& hi) {
    asm("mov.b64 {%0, %1}, %2;" : "=f"(lo), "=f"(hi) : "l"(a));
}
__device__ __forceinline__ u64 fma2(u64 a, u64 b, u64 c) {
    u64 d;
    asm("fma.rn.f32x2 %0, %1, %2, %3;" : "=l"(d) : "l"(a), "l"(b), "l"(c));
    return d;
}
__device__ __forceinline__ u64 mul2(u64 a, u64 b) {
    u64 d;
    asm("mul.rn.f32x2 %0, %1, %2;" : "=l"(d) : "l"(a), "l"(b));
    return d;
}
__device__ __forceinline__ u64 add2(u64 a, u64 b) {
    u64 d;
    asm("add.rn.f32x2 %0, %1, %2;" : "=l"(d) : "l"(a), "l"(b));
    return d;
}

__host__ __device__ constexpr int PC4(int t) {
    return (t & 1) + ((t >> 1) & 1) + ((t >> 2) & 1) + ((t >> 3) & 1);
}
__host__ __device__ constexpr int PC3(int a) {
    return (a & 1) + ((a >> 1) & 1) + ((a >> 2) & 1);
}

// Compile-time group-index tables. Even-parity set {0,3,5,6}, odd {1,2,4,7};
// order = (a asc, b asc) matching the phase-3 enumeration.
__device__ const signed char E_IDX[8][8] = {
    //        0   1   2   3   4   5   6   7
    /*0*/ { -1, -1, -1,  0, -1,  1,  2, -1 },
    /*1*/ { -1, -1,  3, -1,  4, -1, -1,  5 },
    /*2*/ { -1, -1, -1, -1,  6, -1, -1,  7 },
    /*3*/ { -1, -1, -1, -1, -1,  8,  9, -1 },
    /*4*/ { -1, -1, -1, -1, -1, -1, -1, 10 },
    /*5*/ { -1, -1, -1, -1, -1, -1, 11, -1 },
    /*6*/ { -1, -1, -1, -1, -1, -1, -1, -1 },
    /*7*/ { -1, -1, -1, -1, -1, -1, -1, -1 },
};
__device__ const signed char O_IDX[8][8] = {
    //        0   1   2   3   4   5   6   7
    /*0*/ { -1,  0,  1, -1,  2, -1, -1,  3 },
    /*1*/ { -1, -1, -1,  4, -1,  5,  6, -1 },
    /*2*/ { -1, -1, -1,  7, -1,  8,  9, -1 },
    /*3*/ { -1, -1, -1, -1, 10, -1, -1, 11 },
    /*4*/ { -1, -1, -1, -1, -1, 12, 13, -1 },
    /*5*/ { -1, -1, -1, -1, -1, -1, -1, 14 },
    /*6*/ { -1, -1, -1, -1, -1, -1, -1, 15 },
    /*7*/ { -1, -1, -1, -1, -1, -1, -1, -1 },
};

// cross-block handoff state. g_flag/g_done are reset to 0 by the LAST
// consuming block each launch, so graph replays always start clean.
__device__ __align__(16) float g_C[36 * 8];
__device__ int g_flag;
__device__ int g_done;

// One circuit layer applied to TWO independent shuffle-distributed columns
// (r0,r1 | q0,q1); independent chains issue in each other's SHFL shadow.
// Lane bits 4..1 = qubits 0..3, lane bit 0 = qubit 4, register idx = qubit 5.
__device__ __forceinline__ void layer_step2(float& r0, float& r1,
                                            float& q0, float& q1, int lane,
                                            const float* ws, const float* wc) {
    // CNOT ring: (0,1)(1,2)(2,3)(3,4) in lane bits
#pragma unroll
    for (int w = 0; w < 4; w++) {
        const int cm = 16 >> w, tm = 8 >> w;
        float t0 = __shfl_xor_sync(FULL, r0, tm);
        float t1 = __shfl_xor_sync(FULL, r1, tm);
        float u0 = __shfl_xor_sync(FULL, q0, tm);
        float u1 = __shfl_xor_sync(FULL, q1, tm);
        if (lane & cm) { r0 = t0; r1 = t1; q0 = u0; q1 = u1; }
    }
    // (4,5): control lane bit0, target in-register
    if (lane & 1) {
        float t = r0; r0 = r1; r1 = t;
        t = q0; q0 = q1; q1 = t;
    }
    // (5,0): control r-index, target lane bit4
    r1 = __shfl_xor_sync(FULL, r1, 16);
    q1 = __shfl_xor_sync(FULL, q1, 16);
    // RY on qubits 0..4 (lane bits), then qubit 5 (in-register)
#pragma unroll
    for (int w = 0; w < 5; w++) {
        const int m = 16 >> w;
        float o0 = __shfl_xor_sync(FULL, r0, m);
        float o1 = __shfl_xor_sync(FULL, r1, m);
        float p0 = __shfl_xor_sync(FULL, q0, m);
        float p1 = __shfl_xor_sync(FULL, q1, m);
        float sg = (lane & m) ? ws[w] : -ws[w];
        r0 = fmaf(sg, o0, wc[w] * r0);
        r1 = fmaf(sg, o1, wc[w] * r1);
        q0 = fmaf(sg, p0, wc[w] * q0);
        q1 = fmaf(sg, p1, wc[w] * q1);
    }
    {
        float n0 = fmaf(-ws[5], r1, wc[5] * r0);
        float n1 = fmaf(ws[5], r0, wc[5] * r1);
        r0 = n0; r1 = n1;
        n0 = fmaf(-ws[5], q1, wc[5] * q0);
        n1 = fmaf(ws[5], q0, wc[5] * q1);
        q0 = n0; q1 = n1;
    }
}

// ---------------------------------------------------------------------------
// Single kernel, 128 blocks x 512 threads (1 block/SM, all resident in wave 1
// -> the spin-wait is deadlock-free). Block 0 computes the quadratic-form
// coefficient table (shuffle prep + bake) and publishes it via g_C + g_flag;
// other blocks spin, stage it to smem, then all blocks run the per-sample
// quadratic form. Last consumer resets the flag for graph replays.
// ---------------------------------------------------------------------------
__global__ void __launch_bounds__(512) qone_kernel(
    const float* __restrict__ x,
    const float* __restrict__ W,
    const float* __restrict__ ab,
    float* __restrict__ out,
    int nlayers, int B)
{
    __shared__ __align__(16) float sM[16][68];   // rows 16B-aligned (block 0)
    __shared__ __align__(16) float sC[36 * 8];

    const int tid = threadIdx.x;
    const int lane = tid & 31;
    const int wp = tid >> 5;
    const int gid = blockIdx.x * 512 + tid;
    const int nblk = (int)gridDim.x;

    // issue the sample load immediately; DRAM latency hides under prep/spin
    float4 xv = make_float4(0.f, 0.f, 0.f, 0.f);
    if (gid < B) xv = reinterpret_cast<const float4*>(x)[gid];

    if (blockIdx.x == 0) {
        // ---------- prep: 8 warps, 2 basis columns each ----------
        if (wp < 8) {
            float2 abv = *reinterpret_cast<const float2*>(ab);
            float ca0, sa0, ca1, sa1;
            __sincosf(0.5f * abv.x, &sa0, &ca0);
            __sincosf(0.5f * abv.y, &sa1, &ca1);
            float Ae0 = ca0 * ca1, Ae1 = ca0 * sa1;  // q4=0
            float Ao0 = sa0 * ca1, Ao1 = sa0 * sa1;  // q4=1
            const bool hitR = ((lane >> 1) == wp);        // column wp
            const bool hitQ = ((lane >> 1) == wp + 8);    // column wp+8
            float r0, r1, q0, q1;
            if (lane & 1) {
                r0 = hitR ? Ao0 : 0.f; r1 = hitR ? Ao1 : 0.f;
                q0 = hitQ ? Ao0 : 0.f; q1 = hitQ ? Ao1 : 0.f;
            } else {
                r0 = hitR ? Ae0 : 0.f; r1 = hitR ? Ae1 : 0.f;
                q0 = hitQ ? Ae0 : 0.f; q1 = hitQ ? Ae1 : 0.f;
            }

            if (nlayers == 2) {
                const float4* W4 = reinterpret_cast<const float4*>(W);
                float4 wv0 = W4[0], wv1 = W4[1], wv2 = W4[2];
                float wsa[6], wca[6], wsb[6], wcb[6];
                __sincosf(0.5f * wv0.x, &wsa[0], &wca[0]);
                __sincosf(0.5f * wv0.y, &wsa[1], &wca[1]);
                __sincosf(0.5f * wv0.z, &wsa[2], &wca[2]);
                __sincosf(0.5f * wv0.w, &wsa[3], &wca[3]);
                __sincosf(0.5f * wv1.x, &wsa[4], &wca[4]);
                __sincosf(0.5f * wv1.y, &wsa[5], &wca[5]);
                __sincosf(0.5f * wv1.z, &wsb[0], &wcb[0]);
                __sincosf(0.5f * wv1.w, &wsb[1], &wcb[1]);
                __sincosf(0.5f * wv2.x, &wsb[2], &wcb[2]);
                __sincosf(0.5f * wv2.y, &wsb[3], &wcb[3]);
                __sincosf(0.5f * wv2.z, &wsb[4], &wcb[4]);
                __sincosf(0.5f * wv2.w, &wsb[5], &wcb[5]);
                layer_step2(r0, r1, q0, q1, lane, wsa, wca);
                layer_step2(r0, r1, q0, q1, lane, wsb, wcb);
            } else {
                for (int l = 0; l < nlayers; l++) {
                    float ws[6], wc[6];
#pragma unroll
                    for (int w = 0; w < 6; w++)
                        __sincosf(0.5f * __ldg(&W[l * 6 + w]), &ws[w], &wc[w]);
                    layer_step2(r0, r1, q0, q1, lane, ws, wc);
                }
            }
            sM[wp][2 * lane]         = r0;  // b bit0 = qubit5
            sM[wp][2 * lane + 1]     = r1;
            sM[wp + 8][2 * lane]     = q0;
            sM[wp + 8][2 * lane + 1] = q1;
        }
        __syncthreads();

        // ---------- bake table -> sC (local use) AND g_C (publish) ----------
        if (tid < 256) {
            const int t = tid >> 4, tb = tid & 15;
            if (t <= tb && (((PC4(t) ^ PC4(tb)) & 1) == 0)) {
                float a0 = 0.f, a1 = 0.f, a2 = 0.f, a3 = 0.f;
#pragma unroll
                for (int i = 0; i < 16; i++) {
                    float4 u = *reinterpret_cast<const float4*>(&sM[t][4 * i]);
                    float4 v = *reinterpret_cast<const float4*>(&sM[tb][4 * i]);
                    float pr = u.x * v.x + u.y * v.y + u.z * v.z + u.w * v.w;
                    const int b = 4 * i;
                    a0 += (b & 32) ? -pr : pr;  // qubit 0
                    a1 += (b & 16) ? -pr : pr;  // qubit 1
                    a2 += (b & 8)  ? -pr : pr;  // qubit 2
                    a3 += (b & 4)  ? -pr : pr;  // qubit 3
                }
                const int d = (PC4(t) - PC4(tb)) & 3;  // chi = +1 / -1
                const float f = (d == 0 ? 1.f : -1.f) * (t == tb ? 1.f : 2.f);
                const int a = t >> 1, i2 = t & 1, b2 = tb >> 1, jj = tb & 1;
                int j, slot;
                if (a == b2)       { j = a;                       slot = i2; }
                else if (i2 == jj) { j = 8 + (int)E_IDX[a][b2];   slot = i2; }
                else               { j = 20 + (int)O_IDX[a][b2];  slot = i2; }
                const float v0 = f * a0, v1 = f * a1, v2 = f * a2, v3 = f * a3;
                sC[j * 8 + 0 + slot] = v0;  g_C[j * 8 + 0 + slot] = v0;
                sC[j * 8 + 2 + slot] = v1;  g_C[j * 8 + 2 + slot] = v1;
                sC[j * 8 + 4 + slot] = v2;  g_C[j * 8 + 4 + slot] = v2;
                sC[j * 8 + 6 + slot] = v3;  g_C[j * 8 + 6 + slot] = v3;
            }
        }
        __syncthreads();
        if (tid == 0) {
            __threadfence();                 // publish g_C before flag
            atomicExch(&g_flag, 1);
            int dcnt = atomicAdd(&g_done, 1);
            if (dcnt == nblk - 1) { g_done = 0; atomicExch(&g_flag, 0); }
        }
    } else {
        // ---------- consumers: spin until table published, then stage ----------
        if (tid == 0) {
            while (atomicAdd(&g_flag, 0) == 0) {}
            __threadfence();                 // acquire g_C
        }
        __syncthreads();
        if (tid < 72)
            reinterpret_cast<float4*>(sC)[tid] =
                reinterpret_cast<const float4*>(g_C)[tid];
        __syncthreads();
        if (tid == 0) {
            // consumption complete for this block; last consumer resets state
            int dcnt = atomicAdd(&g_done, 1);
            if (dcnt == nblk - 1) { g_done = 0; atomicExch(&g_flag, 0); }
        }
    }

    // ---------------- per-sample quadratic form ----------------
    if (gid >= B) return;

    float c0, s0, c1, s1, c2, s2, c3, s3;
    __sincosf(0.5f * xv.x, &s0, &c0);
    __sincosf(0.5f * xv.y, &s1, &c1);
    __sincosf(0.5f * xv.z, &s2, &c2);
    __sincosf(0.5f * xv.w, &s3, &c3);

    float f0[2] = {c0, s0}, f1[2] = {c1, s1}, f2[2] = {c2, s2};
    float t2a[4], t3a[8];
#pragma unroll
    for (int a = 0; a < 2; a++)
#pragma unroll
        for (int b = 0; b < 2; b++) t2a[a * 2 + b] = f0[a] * f1[b];
#pragma unroll
    for (int a = 0; a < 4; a++)
#pragma unroll
        for (int b = 0; b < 2; b++) t3a[a * 2 + b] = t2a[a] * f2[b];

    const u64 cs3 = pk2(c3, s3);
    const u64 sc3 = pk2(s3, c3);
    u64 Tp[8], Ts[8];  // Tp[a] = (T[2a], T[2a+1]),  Ts[a] = swapped
#pragma unroll
    for (int a = 0; a < 8; a++) {
        u64 dd = pk2(t3a[a], t3a[a]);
        Tp[a] = mul2(dd, cs3);
        Ts[a] = mul2(dd, sc3);
    }

    // 8 accumulator chains (4 outputs x 2 halves by group parity) -> chain
    // depth 18 instead of 36 for this latency-bound regime.
    u64 acc0e = 0ULL, acc1e = 0ULL, acc2e = 0ULL, acc3e = 0ULL;
    u64 acc0o = 0ULL, acc1o = 0ULL, acc2o = 0ULL, acc3o = 0ULL;

#define ACCUM(J, PP) do {                                                     \
        u64 pp_ = (PP);                                                       \
        const ulonglong2* q_ = reinterpret_cast<const ulonglong2*>(&sC[(J) * 8]); \
        ulonglong2 qa_ = q_[0], qb_ = q_[1];                                  \
        if (((J) & 1) == 0) {                                                 \
            acc0e = fma2(qa_.x, pp_, acc0e);                                  \
            acc1e = fma2(qa_.y, pp_, acc1e);                                  \
            acc2e = fma2(qb_.x, pp_, acc2e);                                  \
            acc3e = fma2(qb_.y, pp_, acc3e);                                  \
        } else {                                                              \
            acc0o = fma2(qa_.x, pp_, acc0o);                                  \
            acc1o = fma2(qa_.y, pp_, acc1o);                                  \
            acc2o = fma2(qb_.x, pp_, acc2o);                                  \
            acc3o = fma2(qb_.y, pp_, acc3o);                                  \
        }                                                                     \
    } while (0)

    // diag groups j = 0..7:  (T2a^2, T2a+1^2)
#pragma unroll
    for (int a = 0; a < 8; a++) ACCUM(a, mul2(Tp[a], Tp[a]));
    // E groups j = 8..19: (T2a*T2b, T2a+1*T2b+1), same pc3 parity
    {
        int j = 8;
#pragma unroll
        for (int a = 0; a < 8; a++)
#pragma unroll
            for (int b = a + 1; b < 8; b++)
                if (((PC3(a) ^ PC3(b)) & 1) == 0) { ACCUM(j, mul2(Tp[a], Tp[b])); j++; }
    }
    // O groups j = 20..35: (T2a*T2b+1, T2a+1*T2b), different pc3 parity
    {
        int j = 20;
#pragma unroll
        for (int a = 0; a < 8; a++)
#pragma unroll
            for (int b = a + 1; b < 8; b++)
                if (((PC3(a) ^ PC3(b)) & 1) == 1) { ACCUM(j, mul2(Tp[a], Ts[b])); j++; }
    }
#undef ACCUM

    const u64 acc0 = add2(acc0e, acc0o);
    const u64 acc1 = add2(acc1e, acc1o);
    const u64 acc2 = add2(acc2e, acc2o);
    const u64 acc3 = add2(acc3e, acc3o);

    float lo, hi;
    float4 o;
    upk2(acc0, lo, hi); o.x = lo + hi;
    upk2(acc1, lo, hi); o.y = lo + hi;
    upk2(acc2, lo, hi); o.z = lo + hi;
    upk2(acc3, lo, hi); o.w = lo + hi;
    reinterpret_cast<float4*>(out)[gid] = o;
}

extern "C" void kernel_launch(void* const* d_in, const int* in_sizes, int n_in,
                              void* d_out, int out_size) {
    const float* x  = (const float*)d_in[0];   // (B, 4)
    const float* W  = (const float*)d_in[1];   // (NL, 6)
    const float* ab = (const float*)d_in[2];   // (2,)
    float* out = (float*)d_out;                // (B, 4)
    const int B = in_sizes[0] / 4;
    const int nlayers = in_sizes[1] / 6;
    const int threads = 512;
    const int blocks = (B + threads - 1) / threads;   // 128 for B=65536
    qone_kernel<<<blocks, threads>>>(x, W, ab, out, nlayers, B);
}

// round 15
// speedup vs baseline: 1.0030x; 1.0030x over previous
#include <cuda_runtime.h>

typedef unsigned long long u64;
static const unsigned FULL = 0xFFFFFFFFu;

// ---- packed f32x2 helpers ----
__device__ __forceinline__ u64 pk2(float lo, float hi) {
    u64 r;
    asm("mov.b64 %0, {%1, %2};" : "=l"(r) : "f"(lo), "f"(hi));
    return r;
}
__device__ __forceinline__ void upk2(u64 a, float& lo, float& hi) {
    asm("mov.b64 {%0, %1}, %2;" : "=f"(lo), "=f"(hi) : "l"(a));
}
__device__ __forceinline__ u64 fma2(u64 a, u64 b, u64 c) {
    u64 d;
    asm("fma.rn.f32x2 %0, %1, %2, %3;" : "=l"(d) : "l"(a), "l"(b), "l"(c));
    return d;
}
__device__ __forceinline__ u64 mul2(u64 a, u64 b) {
    u64 d;
    asm("mul.rn.f32x2 %0, %1, %2;" : "=l"(d) : "l"(a), "l"(b));
    return d;
}
__device__ __forceinline__ u64 add2(u64 a, u64 b) {
    u64 d;
    asm("add.rn.f32x2 %0, %1, %2;" : "=l"(d) : "l"(a), "l"(b));
    return d;
}

__host__ __device__ constexpr int PC4(int t) {
    return (t & 1) + ((t >> 1) & 1) + ((t >> 2) & 1) + ((t >> 3) & 1);
}
__host__ __device__ constexpr int PC3(int a) {
    return (a & 1) + ((a >> 1) & 1) + ((a >> 2) & 1);
}

// Compile-time group-index tables. Even-parity set {0,3,5,6}, odd {1,2,4,7};
// order = (a asc, b asc) matching the main-loop enumeration.
__device__ const signed char E_IDX[8][8] = {
    //        0   1   2   3   4   5   6   7
    /*0*/ { -1, -1, -1,  0, -1,  1,  2, -1 },
    /*1*/ { -1, -1,  3, -1,  4, -1, -1,  5 },
    /*2*/ { -1, -1, -1, -1,  6, -1, -1,  7 },
    /*3*/ { -1, -1, -1, -1, -1,  8,  9, -1 },
    /*4*/ { -1, -1, -1, -1, -1, -1, -1, 10 },
    /*5*/ { -1, -1, -1, -1, -1, -1, 11, -1 },
    /*6*/ { -1, -1, -1, -1, -1, -1, -1, -1 },
    /*7*/ { -1, -1, -1, -1, -1, -1, -1, -1 },
};
__device__ const signed char O_IDX[8][8] = {
    //        0   1   2   3   4   5   6   7
    /*0*/ { -1,  0,  1, -1,  2, -1, -1,  3 },
    /*1*/ { -1, -1, -1,  4, -1,  5,  6, -1 },
    /*2*/ { -1, -1, -1,  7, -1,  8,  9, -1 },
    /*3*/ { -1, -1, -1, -1, 10, -1, -1, 11 },
    /*4*/ { -1, -1, -1, -1, -1, 12, 13, -1 },
    /*5*/ { -1, -1, -1, -1, -1, -1, -1, 14 },
    /*6*/ { -1, -1, -1, -1, -1, -1, -1, 15 },
    /*7*/ { -1, -1, -1, -1, -1, -1, -1, -1 },
};

// coefficient table in global scratch (written by prep, read by main)
__device__ __align__(16) float g_C[36 * 8];

// One circuit layer applied to TWO independent shuffle-distributed columns
// (r0,r1 | q0,q1); independent chains issue in each other's SHFL shadow.
// Lane bits 4..1 = qubits 0..3, lane bit 0 = qubit 4, register idx = qubit 5.
__device__ __forceinline__ void layer_step2(float& r0, float& r1,
                                            float& q0, float& q1, int lane,
                                            const float* ws, const float* wc) {
    // CNOT ring: (0,1)(1,2)(2,3)(3,4) in lane bits
#pragma unroll
    for (int w = 0; w < 4; w++) {
        const int cm = 16 >> w, tm = 8 >> w;
        float t0 = __shfl_xor_sync(FULL, r0, tm);
        float t1 = __shfl_xor_sync(FULL, r1, tm);
        float u0 = __shfl_xor_sync(FULL, q0, tm);
        float u1 = __shfl_xor_sync(FULL, q1, tm);
        if (lane & cm) { r0 = t0; r1 = t1; q0 = u0; q1 = u1; }
    }
    // (4,5): control lane bit0, target in-register
    if (lane & 1) {
        float t = r0; r0 = r1; r1 = t;
        t = q0; q0 = q1; q1 = t;
    }
    // (5,0): control r-index, target lane bit4
    r1 = __shfl_xor_sync(FULL, r1, 16);
    q1 = __shfl_xor_sync(FULL, q1, 16);
    // RY on qubits 0..4 (lane bits), then qubit 5 (in-register)
#pragma unroll
    for (int w = 0; w < 5; w++) {
        const int m = 16 >> w;
        float o0 = __shfl_xor_sync(FULL, r0, m);
        float o1 = __shfl_xor_sync(FULL, r1, m);
        float p0 = __shfl_xor_sync(FULL, q0, m);
        float p1 = __shfl_xor_sync(FULL, q1, m);
        float sg = (lane & m) ? ws[w] : -ws[w];
        r0 = fmaf(sg, o0, wc[w] * r0);
        r1 = fmaf(sg, o1, wc[w] * r1);
        q0 = fmaf(sg, p0, wc[w] * q0);
        q1 = fmaf(sg, p1, wc[w] * q1);
    }
    {
        float n0 = fmaf(-ws[5], r1, wc[5] * r0);
        float n1 = fmaf(ws[5], r0, wc[5] * r1);
        r0 = n0; r1 = n1;
        n0 = fmaf(-ws[5], q1, wc[5] * q0);
        n1 = fmaf(ws[5], q0, wc[5] * q1);
        q0 = n0; q1 = n1;
    }
}

// ---------------------------------------------------------------------------
// Prep kernel: 1 block, 256 threads. Warp wp propagates basis columns wp and
// wp+8; then 256 threads bake the quadratic-form table into g_C. Signals
// dependent-launch completion (PDL) after publishing.
// ---------------------------------------------------------------------------
__global__ void __launch_bounds__(256) prep_kernel(
    const float* __restrict__ W,
    const float* __restrict__ ab,
    int nlayers)
{
    __shared__ __align__(16) float sM[16][68];   // rows 16B-aligned

    const int tid = threadIdx.x;
    const int lane = tid & 31;
    const int wp = tid >> 5;

    {
        float2 abv = *reinterpret_cast<const float2*>(ab);
        float ca0, sa0, ca1, sa1;
        __sincosf(0.5f * abv.x, &sa0, &ca0);
        __sincosf(0.5f * abv.y, &sa1, &ca1);
        float Ae0 = ca0 * ca1, Ae1 = ca0 * sa1;  // q4=0
        float Ao0 = sa0 * ca1, Ao1 = sa0 * sa1;  // q4=1
        const bool hitR = ((lane >> 1) == wp);        // column wp
        const bool hitQ = ((lane >> 1) == wp + 8);    // column wp+8
        float r0, r1, q0, q1;
        if (lane & 1) {
            r0 = hitR ? Ao0 : 0.f; r1 = hitR ? Ao1 : 0.f;
            q0 = hitQ ? Ao0 : 0.f; q1 = hitQ ? Ao1 : 0.f;
        } else {
            r0 = hitR ? Ae0 : 0.f; r1 = hitR ? Ae1 : 0.f;
            q0 = hitQ ? Ae0 : 0.f; q1 = hitQ ? Ae1 : 0.f;
        }

        if (nlayers == 2) {
            const float4* W4 = reinterpret_cast<const float4*>(W);
            float4 wv0 = W4[0], wv1 = W4[1], wv2 = W4[2];
            float wsa[6], wca[6], wsb[6], wcb[6];
            __sincosf(0.5f * wv0.x, &wsa[0], &wca[0]);
            __sincosf(0.5f * wv0.y, &wsa[1], &wca[1]);
            __sincosf(0.5f * wv0.z, &wsa[2], &wca[2]);
            __sincosf(0.5f * wv0.w, &wsa[3], &wca[3]);
            __sincosf(0.5f * wv1.x, &wsa[4], &wca[4]);
            __sincosf(0.5f * wv1.y, &wsa[5], &wca[5]);
            __sincosf(0.5f * wv1.z, &wsb[0], &wcb[0]);
            __sincosf(0.5f * wv1.w, &wsb[1], &wcb[1]);
            __sincosf(0.5f * wv2.x, &wsb[2], &wcb[2]);
            __sincosf(0.5f * wv2.y, &wsb[3], &wcb[3]);
            __sincosf(0.5f * wv2.z, &wsb[4], &wcb[4]);
            __sincosf(0.5f * wv2.w, &wsb[5], &wcb[5]);
            layer_step2(r0, r1, q0, q1, lane, wsa, wca);
            layer_step2(r0, r1, q0, q1, lane, wsb, wcb);
        } else {
            for (int l = 0; l < nlayers; l++) {
                float ws[6], wc[6];
#pragma unroll
                for (int w = 0; w < 6; w++)
                    __sincosf(0.5f * __ldg(&W[l * 6 + w]), &ws[w], &wc[w]);
                layer_step2(r0, r1, q0, q1, lane, ws, wc);
            }
        }
        sM[wp][2 * lane]         = r0;  // b bit0 = qubit5
        sM[wp][2 * lane + 1]     = r1;
        sM[wp + 8][2 * lane]     = q0;
        sM[wp + 8][2 * lane + 1] = q1;
    }
    __syncthreads();

    // coefficient table (LDS.128-vectorized) -> global
    {
        const int t = tid >> 4, tb = tid & 15;
        if (t <= tb && (((PC4(t) ^ PC4(tb)) & 1) == 0)) {
            float a0 = 0.f, a1 = 0.f, a2 = 0.f, a3 = 0.f;
#pragma unroll
            for (int i = 0; i < 16; i++) {
                float4 u = *reinterpret_cast<const float4*>(&sM[t][4 * i]);
                float4 v = *reinterpret_cast<const float4*>(&sM[tb][4 * i]);
                float pr = u.x * v.x + u.y * v.y + u.z * v.z + u.w * v.w;
                const int b = 4 * i;
                a0 += (b & 32) ? -pr : pr;  // qubit 0
                a1 += (b & 16) ? -pr : pr;  // qubit 1
                a2 += (b & 8)  ? -pr : pr;  // qubit 2
                a3 += (b & 4)  ? -pr : pr;  // qubit 3
            }
            const int d = (PC4(t) - PC4(tb)) & 3;  // chi = +1 (d==0) / -1 (d==2)
            const float f = (d == 0 ? 1.f : -1.f) * (t == tb ? 1.f : 2.f);
            const int a = t >> 1, i2 = t & 1, b2 = tb >> 1, jj = tb & 1;
            int j, slot;
            if (a == b2)       { j = a;                       slot = i2; }
            else if (i2 == jj) { j = 8 + (int)E_IDX[a][b2];   slot = i2; }
            else               { j = 20 + (int)O_IDX[a][b2];  slot = i2; }
            g_C[j * 8 + 0 + slot] = f * a0;
            g_C[j * 8 + 2 + slot] = f * a1;
            g_C[j * 8 + 4 + slot] = f * a2;
            g_C[j * 8 + 6 + slot] = f * a3;
        }
    }
    // publish g_C, then allow the dependent (PDL) main kernel to proceed
    __threadfence();
    __syncthreads();
    asm volatile("griddepcontrol.launch_dependents;");
}

// ---------------------------------------------------------------------------
// Main kernel: 256 threads/block, TWO threads per sample (half h computes
// outputs 2h, 2h+1). PDL: the prologue (x load, sincos, T build) runs before
// griddepcontrol.wait, overlapping the prep kernel; the g_C staging happens
// after the wait. Without the PDL attribute the wait is a no-op (safe
// fallback, ordering then comes from stream order).
// ---------------------------------------------------------------------------
__global__ void __launch_bounds__(256) qmain_kernel(
    const float* __restrict__ x, float* __restrict__ out, int B)
{
    __shared__ __align__(16) float sC[36 * 8];

    const int tid = threadIdx.x;
    const int half = tid & 1;                      // output-pair selector
    const int gid = (blockIdx.x * 256 + tid) >> 1; // sample index

    float4 xv = make_float4(0.f, 0.f, 0.f, 0.f);
    if (gid < B) xv = reinterpret_cast<const float4*>(x)[gid];

    float c0, s0, c1, s1, c2, s2, c3, s3;
    __sincosf(0.5f * xv.x, &s0, &c0);
    __sincosf(0.5f * xv.y, &s1, &c1);
    __sincosf(0.5f * xv.z, &s2, &c2);
    __sincosf(0.5f * xv.w, &s3, &c3);

    float f0[2] = {c0, s0}, f1[2] = {c1, s1}, f2[2] = {c2, s2};
    float t2a[4], t3a[8];
#pragma unroll
    for (int a = 0; a < 2; a++)
#pragma unroll
        for (int b = 0; b < 2; b++) t2a[a * 2 + b] = f0[a] * f1[b];
#pragma unroll
    for (int a = 0; a < 4; a++)
#pragma unroll
        for (int b = 0; b < 2; b++) t3a[a * 2 + b] = t2a[a] * f2[b];

    const u64 cs3 = pk2(c3, s3);
    const u64 sc3 = pk2(s3, c3);
    u64 Tp[8], Ts[8];  // Tp[a] = (T[2a], T[2a+1]),  Ts[a] = swapped
#pragma unroll
    for (int a = 0; a < 8; a++) {
        u64 dd = pk2(t3a[a], t3a[a]);
        Tp[a] = mul2(dd, cs3);
        Ts[a] = mul2(dd, sc3);
    }

    // wait for prep's published table (no-op without PDL attribute)
    asm volatile("griddepcontrol.wait;");
    if (tid < 72)
        reinterpret_cast<float4*>(sC)[tid] =
            reinterpret_cast<const float4*>(g_C)[tid];
    __syncthreads();

    if (gid >= B) return;

    // this thread accumulates outputs (2*half, 2*half+1); e/o split halves
    // the accumulation chain depth (18 instead of 36).
    const float* sCh = sC + 4 * half;
    u64 accAe = 0ULL, accBe = 0ULL, accAo = 0ULL, accBo = 0ULL;

#define ACCUM(J, PP) do {                                                     \
        u64 pp_ = (PP);                                                       \
        ulonglong2 q_ = *reinterpret_cast<const ulonglong2*>(&sCh[(J) * 8]);  \
        if (((J) & 1) == 0) {                                                 \
            accAe = fma2(q_.x, pp_, accAe);                                   \
            accBe = fma2(q_.y, pp_, accBe);                                   \
        } else {                                                              \
            accAo = fma2(q_.x, pp_, accAo);                                   \
            accBo = fma2(q_.y, pp_, accBo);                                   \
        }                                                                     \
    } while (0)

    // diag groups j = 0..7:  (T2a^2, T2a+1^2)
#pragma unroll
    for (int a = 0; a < 8; a++) ACCUM(a, mul2(Tp[a], Tp[a]));
    // E groups j = 8..19: (T2a*T2b, T2a+1*T2b+1), same pc3 parity
    {
        int j = 8;
#pragma unroll
        for (int a = 0; a < 8; a++)
#pragma unroll
            for (int b = a + 1; b < 8; b++)
                if (((PC3(a) ^ PC3(b)) & 1) == 0) { ACCUM(j, mul2(Tp[a], Tp[b])); j++; }
    }
    // O groups j = 20..35: (T2a*T2b+1, T2a+1*T2b), different pc3 parity
    {
        int j = 20;
#pragma unroll
        for (int a = 0; a < 8; a++)
#pragma unroll
            for (int b = a + 1; b < 8; b++)
                if (((PC3(a) ^ PC3(b)) & 1) == 1) { ACCUM(j, mul2(Tp[a], Ts[b])); j++; }
    }
#undef ACCUM

    const u64 accA = add2(accAe, accAo);
    const u64 accB = add2(accBe, accBo);

    float lo, hi;
    float2 o;
    upk2(accA, lo, hi); o.x = lo + hi;
    upk2(accB, lo, hi); o.y = lo + hi;
    reinterpret_cast<float2*>(out)[2 * gid + half] = o;
}

extern "C" void kernel_launch(void* const* d_in, const int* in_sizes, int n_in,
                              void* d_out, int out_size) {
    const float* x  = (const float*)d_in[0];   // (B, 4)
    const float* W  = (const float*)d_in[1];   // (NL, 6)
    const float* ab = (const float*)d_in[2];   // (2,)
    float* out = (float*)d_out;                // (B, 4)
    const int B = in_sizes[0] / 4;
    const int nlayers = in_sizes[1] / 6;

    prep_kernel<<<1, 256>>>(W, ab, nlayers);

    const int threads = 256;
    const int blocks = (B * 2 + threads - 1) / threads;  // 512 for B=65536

    // Try PDL launch (overlaps main's prologue with prep); fall back to a
    // plain launch if the attribute is rejected under capture.
    cudaLaunchConfig_t cfg = {};
    cfg.gridDim = dim3(blocks, 1, 1);
    cfg.blockDim = dim3(threads, 1, 1);
    cudaLaunchAttribute attrs[1];
    attrs[0].id = cudaLaunchAttributeProgrammaticStreamSerialization;
    attrs[0].val.programmaticStreamSerializationAllowed = 1;
    cfg.attrs = attrs;
    cfg.numAttrs = 1;
    cudaError_t err = cudaLaunchKernelEx(&cfg, qmain_kernel, x, out, B);
    if (err != cudaSuccess) {
        (void)cudaGetLastError();  // clear
        qmain_kernel<<<blocks, threads>>>(x, out, B);
    }
}

// round 17
// speedup vs baseline: 1.2316x; 1.2279x over previous
#include <cuda_runtime.h>

typedef unsigned long long u64;
static const unsigned FULL = 0xFFFFFFFFu;

// ---- packed f32x2 helpers ----
__device__ __forceinline__ u64 pk2(float lo, float hi) {
    u64 r;
    asm("mov.b64 %0, {%1, %2};" : "=l"(r) : "f"(lo), "f"(hi));
    return r;
}
__device__ __forceinline__ void upk2(u64 a, float& lo, float& hi) {
    asm("mov.b64 {%0, %1}, %2;" : "=f"(lo), "=f"(hi) : "l"(a));
}
__device__ __forceinline__ u64 fma2(u64 a, u64 b, u64 c) {
    u64 d;
    asm("fma.rn.f32x2 %0, %1, %2, %3;" : "=l"(d) : "l"(a), "l"(b), "l"(c));
    return d;
}
__device__ __forceinline__ u64 mul2(u64 a, u64 b) {
    u64 d;
    asm("mul.rn.f32x2 %0, %1, %2;" : "=l"(d) : "l"(a), "l"(b));
    return d;
}
__device__ __forceinline__ u64 add2(u64 a, u64 b) {
    u64 d;
    asm("add.rn.f32x2 %0, %1, %2;" : "=l"(d) : "l"(a), "l"(b));
    return d;
}

__host__ __device__ constexpr int PC4(int t) {
    return (t & 1) + ((t >> 1) & 1) + ((t >> 2) & 1) + ((t >> 3) & 1);
}

// ---- 41-term trig-basis index tables (qubit i <-> t bit (3-i)) ----
// A-part = qubits 0,1 (bits 8,4); B-part = qubits 2,3 (bits 2,1).
// Even-A basis order: {1, C0, C1, C0C1, S0S1}; Odd-A: {S0, S1, C0S1, S0C1}.
// D* = sin-qubit mask, O* = cos-qubit mask (sign source).
__device__ const int DAe[5] = {0, 0, 0, 0, 12};
__device__ const int OAe[5] = {0, 8, 4, 12, 0};
__device__ const int DAo[4] = {8, 4, 4, 8};
__device__ const int OAo[4] = {0, 0, 8, 4};
__device__ const int DBe[5] = {0, 0, 0, 0, 3};
__device__ const int OBe[5] = {0, 2, 1, 3, 0};
__device__ const int DBo[4] = {2, 1, 1, 2};
__device__ const int OBo[4] = {0, 0, 2, 1};

// K table in global scratch: 41 basis terms x 4 outputs (float4 rows)
__device__ __align__(16) float g_K[44 * 4];

// One circuit layer applied to TWO independent shuffle-distributed columns
// (r0,r1 | q0,q1); independent chains issue in each other's SHFL shadow.
// Lane bits 4..1 = qubits 0..3, lane bit 0 = qubit 4, register idx = qubit 5.
__device__ __forceinline__ void layer_step2(float& r0, float& r1,
                                            float& q0, float& q1, int lane,
                                            const float* ws, const float* wc) {
    // CNOT ring: (0,1)(1,2)(2,3)(3,4) in lane bits
#pragma unroll
    for (int w = 0; w < 4; w++) {
        const int cm = 16 >> w, tm = 8 >> w;
        float t0 = __shfl_xor_sync(FULL, r0, tm);
        float t1 = __shfl_xor_sync(FULL, r1, tm);
        float u0 = __shfl_xor_sync(FULL, q0, tm);
        float u1 = __shfl_xor_sync(FULL, q1, tm);
        if (lane & cm) { r0 = t0; r1 = t1; q0 = u0; q1 = u1; }
    }
    // (4,5): control lane bit0, target in-register
    if (lane & 1) {
        float t = r0; r0 = r1; r1 = t;
        t = q0; q0 = q1; q1 = t;
    }
    // (5,0): control r-index, target lane bit4
    r1 = __shfl_xor_sync(FULL, r1, 16);
    q1 = __shfl_xor_sync(FULL, q1, 16);
    // RY on qubits 0..4 (lane bits), then qubit 5 (in-register)
#pragma unroll
    for (int w = 0; w < 5; w++) {
        const int m = 16 >> w;
        float o0 = __shfl_xor_sync(FULL, r0, m);
        float o1 = __shfl_xor_sync(FULL, r1, m);
        float p0 = __shfl_xor_sync(FULL, q0, m);
        float p1 = __shfl_xor_sync(FULL, q1, m);
        float sg = (lane & m) ? ws[w] : -ws[w];
        r0 = fmaf(sg, o0, wc[w] * r0);
        r1 = fmaf(sg, o1, wc[w] * r1);
        q0 = fmaf(sg, p0, wc[w] * q0);
        q1 = fmaf(sg, p1, wc[w] * q1);
    }
    {
        float n0 = fmaf(-ws[5], r1, wc[5] * r0);
        float n1 = fmaf(ws[5], r0, wc[5] * r1);
        r0 = n0; r1 = n1;
        n0 = fmaf(-ws[5], q1, wc[5] * q0);
        n1 = fmaf(ws[5], q0, wc[5] * q1);
        q0 = n0; q1 = n1;
    }
}

// ---------------------------------------------------------------------------
// Prep kernel: 1 block, 256 threads.
//  phase 1: warp wp propagates basis columns wp, wp+8 (verified shuffle sim)
//  phase 2: pairwise coefficients C_w(t,t') -> smem sCp[t][t'][4]
//  phase 3: fold half-angle identities into the 41-term K table -> g_K
// ---------------------------------------------------------------------------
__global__ void __launch_bounds__(256) prep_kernel(
    const float* __restrict__ W,
    const float* __restrict__ ab,
    int nlayers)
{
    __shared__ __align__(16) float sM[16][68];       // rows 16B-aligned
    __shared__ __align__(16) float sCp[16][16][4];   // pairwise C (t<=t' valid)

    const int tid = threadIdx.x;
    const int lane = tid & 31;
    const int wp = tid >> 5;

    {
        float2 abv = *reinterpret_cast<const float2*>(ab);
        float ca0, sa0, ca1, sa1;
        __sincosf(0.5f * abv.x, &sa0, &ca0);
        __sincosf(0.5f * abv.y, &sa1, &ca1);
        float Ae0 = ca0 * ca1, Ae1 = ca0 * sa1;  // q4=0
        float Ao0 = sa0 * ca1, Ao1 = sa0 * sa1;  // q4=1
        const bool hitR = ((lane >> 1) == wp);        // column wp
        const bool hitQ = ((lane >> 1) == wp + 8);    // column wp+8
        float r0, r1, q0, q1;
        if (lane & 1) {
            r0 = hitR ? Ao0 : 0.f; r1 = hitR ? Ao1 : 0.f;
            q0 = hitQ ? Ao0 : 0.f; q1 = hitQ ? Ao1 : 0.f;
        } else {
            r0 = hitR ? Ae0 : 0.f; r1 = hitR ? Ae1 : 0.f;
            q0 = hitQ ? Ae0 : 0.f; q1 = hitQ ? Ae1 : 0.f;
        }

        if (nlayers == 2) {
            const float4* W4 = reinterpret_cast<const float4*>(W);
            float4 wv0 = W4[0], wv1 = W4[1], wv2 = W4[2];
            float wsa[6], wca[6], wsb[6], wcb[6];
            __sincosf(0.5f * wv0.x, &wsa[0], &wca[0]);
            __sincosf(0.5f * wv0.y, &wsa[1], &wca[1]);
            __sincosf(0.5f * wv0.z, &wsa[2], &wca[2]);
            __sincosf(0.5f * wv0.w, &wsa[3], &wca[3]);
            __sincosf(0.5f * wv1.x, &wsa[4], &wca[4]);
            __sincosf(0.5f * wv1.y, &wsa[5], &wca[5]);
            __sincosf(0.5f * wv1.z, &wsb[0], &wcb[0]);
            __sincosf(0.5f * wv1.w, &wsb[1], &wcb[1]);
            __sincosf(0.5f * wv2.x, &wsb[2], &wcb[2]);
            __sincosf(0.5f * wv2.y, &wsb[3], &wcb[3]);
            __sincosf(0.5f * wv2.z, &wsb[4], &wcb[4]);
            __sincosf(0.5f * wv2.w, &wsb[5], &wcb[5]);
            layer_step2(r0, r1, q0, q1, lane, wsa, wca);
            layer_step2(r0, r1, q0, q1, lane, wsb, wcb);
        } else {
            for (int l = 0; l < nlayers; l++) {
                float ws[6], wc[6];
#pragma unroll
                for (int w = 0; w < 6; w++)
                    __sincosf(0.5f * __ldg(&W[l * 6 + w]), &ws[w], &wc[w]);
                layer_step2(r0, r1, q0, q1, lane, ws, wc);
            }
        }
        sM[wp][2 * lane]         = r0;  // b bit0 = qubit5
        sM[wp][2 * lane + 1]     = r1;
        sM[wp + 8][2 * lane]     = q0;
        sM[wp + 8][2 * lane + 1] = q1;
    }
    __syncthreads();

    // ---------- phase 2: pairwise coefficients (LDS.128-vectorized) --------
    {
        const int t = tid >> 4, tb = tid & 15;
        if (t <= tb && (((PC4(t) ^ PC4(tb)) & 1) == 0)) {
            float a0 = 0.f, a1 = 0.f, a2 = 0.f, a3 = 0.f;
#pragma unroll
            for (int i = 0; i < 16; i++) {
                float4 u = *reinterpret_cast<const float4*>(&sM[t][4 * i]);
                float4 v = *reinterpret_cast<const float4*>(&sM[tb][4 * i]);
                float pr = u.x * v.x + u.y * v.y + u.z * v.z + u.w * v.w;
                const int b = 4 * i;
                a0 += (b & 32) ? -pr : pr;  // qubit 0
                a1 += (b & 16) ? -pr : pr;  // qubit 1
                a2 += (b & 8)  ? -pr : pr;  // qubit 2
                a3 += (b & 4)  ? -pr : pr;  // qubit 3
            }
            const int d = (PC4(t) - PC4(tb)) & 3;  // chi = +1 (d==0) / -1 (d==2)
            const float f = (d == 0 ? 1.f : -1.f) * (t == tb ? 1.f : 2.f);
            sCp[t][tb][0] = f * a0;
            sCp[t][tb][1] = f * a1;
            sCp[t][tb][2] = f * a2;
            sCp[t][tb][3] = f * a3;
        }
    }
    __syncthreads();

    // ---------- phase 3: fold into the 41-term trig-basis table ----------
    // K_w[k] = (1/16) * sum over ALL unordered pairs (a, b=a^D) of
    //          sign(popc(a & O)) * C_w(a, b).
    // (a > b skipped: each unordered pair once; D=0 -> diagonal once.
    //  sign well-defined: O and D disjoint, so a&O == b&O.)
    if (tid < 41) {
        const int k = tid;
        int DM, OM;
        if (k < 25) {
            const int ae = k / 5, be = k % 5;
            DM = DAe[ae] | DBe[be];
            OM = OAe[ae] | OBe[be];
        } else {
            const int j = k - 25, ao = j / 4, bo = j % 4;
            DM = DAo[ao] | DBo[bo];
            OM = OAo[ao] | OBo[bo];
        }
        float k0 = 0.f, k1 = 0.f, k2 = 0.f, k3 = 0.f;
#pragma unroll
        for (int a = 0; a < 16; a++) {
            const int b = a ^ DM;
            if (a > b) continue;
            const float sg = (__popc((unsigned)(a & OM)) & 1) ? -1.f : 1.f;
            k0 += sg * sCp[a][b][0];
            k1 += sg * sCp[a][b][1];
            k2 += sg * sCp[a][b][2];
            k3 += sg * sCp[a][b][3];
        }
        g_K[k * 4 + 0] = k0 * 0.0625f;
        g_K[k * 4 + 1] = k1 * 0.0625f;
        g_K[k * 4 + 2] = k2 * 0.0625f;
        g_K[k * 4 + 3] = k3 * 0.0625f;
    }
}

// ---------------------------------------------------------------------------
// Main kernel: 256 threads/block, one sample per thread.
// out_w = sum_k K_w[k] * g_k over the 41-term basis; outputs packed (0,1) and
// (2,3) in f32x2 accumulators -> no cross-half reduce at the end.
// ---------------------------------------------------------------------------
__global__ void __launch_bounds__(256) qmain_kernel(
    const float* __restrict__ x, float* __restrict__ out, int B)
{
    __shared__ __align__(16) float4 sK[41];

    const int tid = threadIdx.x;
    const int gid = blockIdx.x * 256 + tid;

    if (tid < 41)
        sK[tid] = reinterpret_cast<const float4*>(g_K)[tid];

    float4 xv = make_float4(0.f, 0.f, 0.f, 0.f);
    if (gid < B) xv = reinterpret_cast<const float4*>(x)[gid];

    // full-angle sincos (no half angles needed in this basis)
    float C0, S0, C1, S1, C2, S2, C3, S3;
    __sincosf(xv.x, &S0, &C0);
    __sincosf(xv.y, &S1, &C1);
    __sincosf(xv.z, &S2, &C2);
    __sincosf(xv.w, &S3, &C3);

    const float C01 = C0 * C1, S01 = S0 * S1, CS01 = C0 * S1, SC01 = S0 * C1;
    const float C23 = C2 * C3, S23 = S2 * S3, CS23 = C2 * S3, SC23 = S2 * C3;

    // duplicated-packed factor arrays; mul2(Ax, Bx) yields (g, g) directly
    u64 Ae[5], Be[5], Ao[4], Bo[4];
    Ae[0] = pk2(1.f, 1.f); Ae[1] = pk2(C0, C0); Ae[2] = pk2(C1, C1);
    Ae[3] = pk2(C01, C01); Ae[4] = pk2(S01, S01);
    Be[0] = pk2(1.f, 1.f); Be[1] = pk2(C2, C2); Be[2] = pk2(C3, C3);
    Be[3] = pk2(C23, C23); Be[4] = pk2(S23, S23);
    Ao[0] = pk2(S0, S0); Ao[1] = pk2(S1, S1);
    Ao[2] = pk2(CS01, CS01); Ao[3] = pk2(SC01, SC01);
    Bo[0] = pk2(S2, S2); Bo[1] = pk2(S3, S3);
    Bo[2] = pk2(CS23, CS23); Bo[3] = pk2(SC23, SC23);

    __syncthreads();
    if (gid >= B) return;

    // acc01 packs outputs (0,1); acc23 packs (2,3); e/o split halves chain depth
    u64 a01e = 0ULL, a01o = 0ULL, a23e = 0ULL, a23o = 0ULL;

#define ACC(K_, GG) do {                                                      \
        u64 gg_ = (GG);                                                       \
        ulonglong2 q_ = *reinterpret_cast<const ulonglong2*>(&sK[(K_)]);      \
        if (((K_) & 1) == 0) {                                                \
            a01e = fma2(q_.x, gg_, a01e);                                     \
            a23e = fma2(q_.y, gg_, a23e);                                     \
        } else {                                                              \
            a01o = fma2(q_.x, gg_, a01o);                                     \
            a23o = fma2(q_.y, gg_, a23o);                                     \
        }                                                                     \
    } while (0)

    // even part: k = ae*5 + be, g = EvenA[ae] * EvenB[be]
#pragma unroll
    for (int ae = 0; ae < 5; ae++)
#pragma unroll
        for (int be = 0; be < 5; be++)
            ACC(ae * 5 + be, mul2(Ae[ae], Be[be]));
    // odd part: k = 25 + ao*4 + bo, g = OddA[ao] * OddB[bo]
#pragma unroll
    for (int ao = 0; ao < 4; ao++)
#pragma unroll
        for (int bo = 0; bo < 4; bo++)
            ACC(25 + ao * 4 + bo, mul2(Ao[ao], Bo[bo]));
#undef ACC

    const u64 a01 = add2(a01e, a01o);
    const u64 a23 = add2(a23e, a23o);

    float4 o;
    upk2(a01, o.x, o.y);
    upk2(a23, o.z, o.w);
    reinterpret_cast<float4*>(out)[gid] = o;
}

extern "C" void kernel_launch(void* const* d_in, const int* in_sizes, int n_in,
                              void* d_out, int out_size) {
    const float* x  = (const float*)d_in[0];   // (B, 4)
    const float* W  = (const float*)d_in[1];   // (NL, 6)
    const float* ab = (const float*)d_in[2];   // (2,)
    float* out = (float*)d_out;                // (B, 4)
    const int B = in_sizes[0] / 4;
    const int nlayers = in_sizes[1] / 6;

    prep_kernel<<<1, 256>>>(W, ab, nlayers);

    const int threads = 256;
    const int blocks = (B + threads - 1) / threads;
    qmain_kernel<<<blocks, threads>>>(x, out, B);
}